// round 2
// baseline (speedup 1.0000x reference)
#include <cuda_runtime.h>

// Loss_Antonymy: out = sum_i relu(1 + sign_i * tanh(||A1_i - S2_i||_2)),
// sign_i = -1 if labels[i]==2 else +1.
// N = 1048576, D = 64. Inputs: S2_out [N*64] f32, A1_out [N*64] f32, labels [N] int32
// (JAX x64 disabled downcasts the requested int64 to int32).
// Output: 1 float.

#define D 64

__global__ void zero_out_kernel(float* out) {
    out[0] = 0.0f;
}

__global__ __launch_bounds__(256, 8)
void loss_antonymy_kernel(const float* __restrict__ S2,
                          const float* __restrict__ A1,
                          const int* __restrict__ labels,
                          float* __restrict__ out,
                          int nrows)
{
    const int lane  = threadIdx.x & 31;
    const int half  = lane >> 4;        // 0 or 1: which row of the pair
    const int sub   = lane & 15;        // position within half-warp (16 float4 = 64 floats)
    const int gwarp = (blockIdx.x * blockDim.x + threadIdx.x) >> 5;
    const int nwarp = (gridDim.x * blockDim.x) >> 5;
    const int npairs = nrows >> 1;      // N is even

    float acc = 0.0f;

    for (int pair = gwarp; pair < npairs; pair += nwarp) {
        const long long row = (long long)pair * 2 + half;
        const float4* a4 = reinterpret_cast<const float4*>(A1 + row * D);
        const float4* s4 = reinterpret_cast<const float4*>(S2 + row * D);

        float4 av = __ldg(&a4[sub]);
        float4 sv = __ldg(&s4[sub]);

        float dx = av.x - sv.x;
        float dy = av.y - sv.y;
        float dz = av.z - sv.z;
        float dw = av.w - sv.w;
        float ss = dx * dx + dy * dy + dz * dz + dw * dw;

        // reduce across the 16 lanes of this half-warp (xor offsets < 16 never
        // cross the bit-4 boundary, so full-width xor shuffles are safe)
        #pragma unroll
        for (int o = 8; o > 0; o >>= 1)
            ss += __shfl_xor_sync(0xffffffffu, ss, o);

        if (sub == 0) {
            float d = sqrtf(ss);
            float t = tanhf(d);
            float sign = (labels[row] == 2) ? -1.0f : 1.0f;
            acc += fmaxf(0.0f, fmaf(sign, t, 1.0f));
        }
    }

    // block reduction: intra-warp, then across warps via shared, one atomic per block
    #pragma unroll
    for (int o = 16; o > 0; o >>= 1)
        acc += __shfl_xor_sync(0xffffffffu, acc, o);

    __shared__ float wsum[8];   // 256 threads -> 8 warps
    const int wid = threadIdx.x >> 5;
    if (lane == 0) wsum[wid] = acc;
    __syncthreads();

    if (wid == 0) {
        float v = (lane < (blockDim.x >> 5)) ? wsum[lane] : 0.0f;
        #pragma unroll
        for (int o = 4; o > 0; o >>= 1)
            v += __shfl_xor_sync(0xffffffffu, v, o);
        if (lane == 0)
            atomicAdd(out, v);
    }
}

extern "C" void kernel_launch(void* const* d_in, const int* in_sizes, int n_in,
                              void* d_out, int out_size)
{
    const float* S2     = (const float*)d_in[0];
    const float* A1     = (const float*)d_in[1];
    const int*   labels = (const int*)d_in[2];
    float*       out    = (float*)d_out;

    const int nrows = in_sizes[2];   // labels element count = N

    zero_out_kernel<<<1, 1>>>(out);

    // Persistent-ish grid: 148 SMs (152 on GB300) * 8 blocks of 256 threads
    const int blocks = 148 * 8;
    loss_antonymy_kernel<<<blocks, 256>>>(S2, A1, labels, out, nrows);
}

// round 3
// speedup vs baseline: 1.0568x; 1.0568x over previous
#include <cuda_runtime.h>

// Loss_Antonymy: out = sum_i relu(1 + sign_i * tanh(||A1_i - S2_i||_2)),
// sign_i = -1 if labels[i]==2 else +1.
// N = 1048576, D = 64. Inputs: S2_out [N*64] f32, A1_out [N*64] f32, labels [N] int32.
// Output: 1 float.
//
// R3: unroll x2 (4 rows per warp iteration), front-batched float4 loads to
// raise per-thread MLP 2 -> 4 and cut loop overhead.

#define D 64

__global__ void zero_out_kernel(float* out) {
    out[0] = 0.0f;
}

__global__ __launch_bounds__(256)
void loss_antonymy_kernel(const float* __restrict__ S2,
                          const float* __restrict__ A1,
                          const int* __restrict__ labels,
                          float* __restrict__ out,
                          int nrows)
{
    const int lane  = threadIdx.x & 31;
    const int half  = lane >> 4;        // 0 or 1: which row within a pair
    const int sub   = lane & 15;        // 16 float4 = 64 floats of one row
    const int gwarp = (blockIdx.x * blockDim.x + threadIdx.x) >> 5;
    const int nwarp = (gridDim.x * blockDim.x) >> 5;
    const int nquads = nrows >> 2;      // 4 rows per warp iteration

    float acc = 0.0f;

    for (int quad = gwarp; quad < nquads; quad += nwarp) {
        const long long row0 = (long long)quad * 4 + half;      // rows {0,1} of quad
        const long long row1 = row0 + 2;                        // rows {2,3} of quad

        const float4* a0 = reinterpret_cast<const float4*>(A1 + row0 * D);
        const float4* s0 = reinterpret_cast<const float4*>(S2 + row0 * D);
        const float4* a1 = reinterpret_cast<const float4*>(A1 + row1 * D);
        const float4* s1 = reinterpret_cast<const float4*>(S2 + row1 * D);

        // front-batch all 4 independent 16B loads (MLP=4 per thread)
        float4 av0 = __ldg(&a0[sub]);
        float4 sv0 = __ldg(&s0[sub]);
        float4 av1 = __ldg(&a1[sub]);
        float4 sv1 = __ldg(&s1[sub]);

        float dx0 = av0.x - sv0.x, dy0 = av0.y - sv0.y;
        float dz0 = av0.z - sv0.z, dw0 = av0.w - sv0.w;
        float ss0 = dx0*dx0 + dy0*dy0 + dz0*dz0 + dw0*dw0;

        float dx1 = av1.x - sv1.x, dy1 = av1.y - sv1.y;
        float dz1 = av1.z - sv1.z, dw1 = av1.w - sv1.w;
        float ss1 = dx1*dx1 + dy1*dy1 + dz1*dz1 + dw1*dw1;

        // reduce each across the 16 lanes of this half-warp
        #pragma unroll
        for (int o = 8; o > 0; o >>= 1) {
            ss0 += __shfl_xor_sync(0xffffffffu, ss0, o);
            ss1 += __shfl_xor_sync(0xffffffffu, ss1, o);
        }

        if (sub == 0) {
            float sign0 = (labels[row0] == 2) ? -1.0f : 1.0f;
            float sign1 = (labels[row1] == 2) ? -1.0f : 1.0f;
            float t0 = tanhf(sqrtf(ss0));
            float t1 = tanhf(sqrtf(ss1));
            acc += fmaxf(0.0f, fmaf(sign0, t0, 1.0f));
            acc += fmaxf(0.0f, fmaf(sign1, t1, 1.0f));
        }
    }

    // block reduction: intra-warp, then across warps via shared, one atomic per block
    #pragma unroll
    for (int o = 16; o > 0; o >>= 1)
        acc += __shfl_xor_sync(0xffffffffu, acc, o);

    __shared__ float wsum[8];   // 256 threads -> 8 warps
    const int wid = threadIdx.x >> 5;
    if (lane == 0) wsum[wid] = acc;
    __syncthreads();

    if (wid == 0) {
        float v = (lane < (blockDim.x >> 5)) ? wsum[lane] : 0.0f;
        #pragma unroll
        for (int o = 4; o > 0; o >>= 1)
            v += __shfl_xor_sync(0xffffffffu, v, o);
        if (lane == 0)
            atomicAdd(out, v);
    }
}

extern "C" void kernel_launch(void* const* d_in, const int* in_sizes, int n_in,
                              void* d_out, int out_size)
{
    const float* S2     = (const float*)d_in[0];
    const float* A1     = (const float*)d_in[1];
    const int*   labels = (const int*)d_in[2];
    float*       out    = (float*)d_out;

    const int nrows = in_sizes[2];   // labels element count = N

    zero_out_kernel<<<1, 1>>>(out);

    const int blocks = 148 * 8;
    loss_antonymy_kernel<<<blocks, 256>>>(S2, A1, labels, out, nrows);
}